// round 8
// baseline (speedup 1.0000x reference)
#include <cuda_runtime.h>
#include <math_constants.h>

#define NN    10000
#define EE    160000
#define ET    170000   // EE + NN self loops
#define SNAP  16       // B*T
#define TT    8
#define BB    2
#define CIN   64
#define CC    32

typedef unsigned long long u64;

// packed f32x2 helpers (Blackwell dual-FP32 pipe)
#define F2ADD(r, x, y)    asm("add.rn.f32x2 %0,%1,%2;"    : "=l"(r) : "l"(x), "l"(y))
#define F2MUL(r, x, y)    asm("mul.rn.f32x2 %0,%1,%2;"    : "=l"(r) : "l"(x), "l"(y))
#define F2FMA(r, x, y, z) asm("fma.rn.f32x2 %0,%1,%2,%3;" : "=l"(r) : "l"(x), "l"(y), "l"(z))
#define F2PK(r, lo, hi)   asm("mov.b64 %0,{%1,%2};"       : "=l"(r) : "f"(lo), "f"(hi))
#define F2UNPK(lo, hi, x) asm("mov.b64 {%0,%1},%2;"       : "=f"(lo), "=f"(hi) : "l"(x))
#define ABSM 0x7FFFFFFF7FFFFFFFULL

// ---------------- static device scratch (zero-initialized at load) ----------------
__device__ float g_xl[NN * SNAP * CC];       // [n][s][c]
__device__ float g_xr[NN * SNAP * CC];       // [n][s][c]
__device__ float g_ee[ET * CC];              // [edge][c]
__device__ float g_loop_sum[NN * 3];
__device__ float g_loop_cnt[NN];
__device__ int   g_cursor[NN];
__device__ int   g_csr_off[NN + 1];
__device__ int2  g_csr[ET];                  // (src, eid)

// ---------------- prep kernels ----------------
// loop_sum/loop_cnt/cursor are zero at entry of every replay: statically
// zero-initialized for the first run, re-zeroed by k_gatgru's epilogue after.

__global__ void k_deg(const int* __restrict__ ei, const float* __restrict__ ea) {
    int e = blockIdx.x * blockDim.x + threadIdx.x;
    if (e >= EE) return;
    int dst = ei[EE + e];
    atomicAdd(&g_loop_sum[dst * 3 + 0], ea[e * 3 + 0]);
    atomicAdd(&g_loop_sum[dst * 3 + 1], ea[e * 3 + 1]);
    atomicAdd(&g_loop_sum[dst * 3 + 2], ea[e * 3 + 2]);
    atomicAdd(&g_loop_cnt[dst], 1.f);
}

// single-block scan: 1024 threads, 10 items each, one-sync shfl scan
__global__ void k_scan() {
    __shared__ int warp_sums[32];
    int tid = threadIdx.x, lane = tid & 31, wid = tid >> 5;
    int base = tid * 10;
    int v[10];
    int s = 0;
#pragma unroll
    for (int k = 0; k < 10; k++) {
        int idx = base + k;
        int val = (idx < NN) ? ((int)g_loop_cnt[idx] + 1) : 0;
        v[k] = s;
        s += val;
    }
    int incl = s;
#pragma unroll
    for (int o = 1; o < 32; o <<= 1) {
        int u = __shfl_up_sync(0xffffffffu, incl, o);
        if (lane >= o) incl += u;
    }
    if (lane == 31) warp_sums[wid] = incl;
    __syncthreads();
    if (tid < 32) {
        int w = warp_sums[tid];
#pragma unroll
        for (int o = 1; o < 32; o <<= 1) {
            int u = __shfl_up_sync(0xffffffffu, w, o);
            if (tid >= o) w += u;
        }
        warp_sums[tid] = w;
    }
    __syncthreads();
    int warp_off = (wid == 0) ? 0 : warp_sums[wid - 1];
    int thr_excl = warp_off + incl - s;
#pragma unroll
    for (int k = 0; k < 10; k++) {
        int idx = base + k;
        if (idx < NN) g_csr_off[idx] = thr_excl + v[k];
    }
    if (tid == 0) g_csr_off[NN] = warp_sums[31];
}

__global__ void k_scatter(const int* __restrict__ ei) {
    int e = blockIdx.x * blockDim.x + threadIdx.x;
    if (e < EE) {
        int src = ei[e];
        int dst = ei[EE + e];
        int pos = g_csr_off[dst] + atomicAdd(&g_cursor[dst], 1);
        g_csr[pos] = make_int2(src, e);
    } else if (e < EE + NN) {
        int n = e - EE;
        int pos = g_csr_off[n + 1] - 1;  // self-loop in the last slot
        g_csr[pos] = make_int2(n, EE + n);
    }
}

// ee[r][c] = attr_r @ W_e (self-loop rows: segment mean of incoming attr)
__global__ void k_ee(const float* __restrict__ edge_attr, const float* __restrict__ W_e) {
    int idx = blockIdx.x * blockDim.x + threadIdx.x;
    int r = idx >> 3, c4 = idx & 7;
    if (r >= ET) return;
    float a0, a1, a2;
    if (r < EE) {
        a0 = edge_attr[r * 3 + 0];
        a1 = edge_attr[r * 3 + 1];
        a2 = edge_attr[r * 3 + 2];
    } else {
        int n = r - EE;
        float cnt = fmaxf(g_loop_cnt[n], 1.f);
        float inv = 1.f / cnt;
        a0 = g_loop_sum[n * 3 + 0] * inv;
        a1 = g_loop_sum[n * 3 + 1] * inv;
        a2 = g_loop_sum[n * 3 + 2] * inv;
    }
    const float4* We4 = (const float4*)W_e;
    float4 w0 = We4[c4], w1 = We4[8 + c4], w2 = We4[16 + c4];
    float4 o;
    o.x = a0 * w0.x + a1 * w1.x + a2 * w2.x;
    o.y = a0 * w0.y + a1 * w1.y + a2 * w2.y;
    o.z = a0 * w0.z + a1 * w1.z + a2 * w2.z;
    o.w = a0 * w0.w + a1 * w1.w + a2 * w2.w;
    ((float4*)g_ee)[r * 8 + c4] = o;
}

// Persistent xl/xr transform; packed {Wl,Wr} float2 smem; 2 rows/warp/iter.
__global__ void __launch_bounds__(256) k_xlr(const float* __restrict__ x,
                      const float* __restrict__ W_l, const float* __restrict__ b_l,
                      const float* __restrict__ W_r, const float* __restrict__ b_r) {
    __shared__ float2 sW[CIN * CC];
    int tid = threadIdx.x;
    for (int i = tid; i < CIN * CC; i += 256)
        sW[i] = make_float2(W_l[i], W_r[i]);
    __syncthreads();
    int lane = tid & 31;
    float bl = b_l[lane], br = b_r[lane];
    int gw = blockIdx.x * 8 + (tid >> 5);
    int stride = gridDim.x * 8 * 2;
    for (int r0 = gw * 2; r0 < SNAP * NN; r0 += stride) {
        const float* xp = x + (long)r0 * CIN;
        float a_x0 = xp[lane], a_x1 = xp[lane + 32];
        float b_x0 = xp[CIN + lane], b_x1 = xp[CIN + lane + 32];
        float al_a = 0.f, ar_a = 0.f, al_b = 0.f, ar_b = 0.f;
#pragma unroll
        for (int k = 0; k < CIN; k++) {
            float xa = (k < 32) ? __shfl_sync(0xffffffffu, a_x0, k)
                                : __shfl_sync(0xffffffffu, a_x1, k - 32);
            float xb = (k < 32) ? __shfl_sync(0xffffffffu, b_x0, k)
                                : __shfl_sync(0xffffffffu, b_x1, k - 32);
            float2 w = sW[k * 32 + lane];
            al_a += xa * w.x; ar_a += xa * w.y;
            al_b += xb * w.x; ar_b += xb * w.y;
        }
        int s0 = r0 / NN, n0 = r0 - s0 * NN;
        int r1 = r0 + 1;
        int s1 = r1 / NN, n1 = r1 - s1 * NN;
        g_xl[(n0 * SNAP + s0) * 32 + lane] = al_a + bl;
        g_xr[(n0 * SNAP + s0) * 32 + lane] = ar_a + br;
        g_xl[(n1 * SNAP + s1) * 32 + lane] = al_b + bl;
        g_xr[(n1 * SNAP + s1) * 32 + lane] = ar_b + br;
    }
}

// Fused GATv2 + GRU, packed-f32x2 math throughout.
__global__ void __launch_bounds__(256, 2) k_gatgru(
        const float* __restrict__ att, const float* __restrict__ bias_gat,
        const float* __restrict__ W_ih, const float* __restrict__ W_hh,
        const float* __restrict__ b_ih, const float* __restrict__ b_hh,
        float* __restrict__ out) {
    // GRU weights stored as (wi, wh) pairs so LDS.128/LDS.64 yield ready f32x2 operands
    __shared__ float4 sWrz[32][32];    // [h][c] = {wi_r, wh_r, wi_z, wh_z}
    __shared__ float2 sWn[32][32];     // [h][c] = {wi_n, wh_n}
    __shared__ float  sb[6][32];
    __shared__ float  s_tr[8][16][32]; // per-warp transpose [warp][s][c]

    int tid = threadIdx.x;
    for (int i = tid; i < 1024; i += 256) {
        int c = i & 31, hh = i >> 5;
        sWrz[hh][c] = make_float4(W_ih[c * 32 + hh],        W_hh[c * 32 + hh],
                                  W_ih[(32 + c) * 32 + hh], W_hh[(32 + c) * 32 + hh]);
        sWn[hh][c] = make_float2(W_ih[(64 + c) * 32 + hh], W_hh[(64 + c) * 32 + hh]);
    }
    if (tid < 96) {
        int g = tid >> 5, c = tid & 31;
        sb[g][c] = b_ih[tid];
        sb[3 + g][c] = b_hh[tid];
    }
    __syncthreads();

    int w = tid >> 5, lane = tid & 31;
    int n = blockIdx.x * 8 + w;            // grid = NN/8 exact
    int q = lane & 7, g = lane >> 3;

    // packed constants
    u64 C06, C04, AT_a, AT_b;
    F2PK(C06, 0.6f, 0.6f);
    F2PK(C04, 0.4f, 0.4f);
    {
        const float4 at4 = *(const float4*)(att + 4 * q);
        F2PK(AT_a, at4.x, at4.y);
        F2PK(AT_b, at4.z, at4.w);
    }

    // xr preload (packed pairs)
    ulonglong2 xr2[4];
    {
        const ulonglong2* p = (const ulonglong2*)(g_xr + n * SNAP * 32);
#pragma unroll
        for (int k = 0; k < 4; k++) xr2[k] = p[k * 32 + lane];
    }

    ulonglong2 acc[4];
#pragma unroll
    for (int k = 0; k < 4; k++) { u64 z; F2PK(z, 0.f, 0.f); acc[k].x = z; acc[k].y = z; }
    float ssum[4] = {0.f, 0.f, 0.f, 0.f};

    int off = g_csr_off[n], end = g_csr_off[n + 1];  // end > off (self-loop)

    ulonglong2 a[4], ev;
    {
        int2 e0 = g_csr[off];
        const ulonglong2* xp = (const ulonglong2*)(g_xl + e0.x * SNAP * 32);
        ev = *(const ulonglong2*)(g_ee + e0.y * 32 + 4 * q);
#pragma unroll
        for (int k = 0; k < 4; k++) a[k] = xp[k * 32 + lane];
    }

    // leaky_relu(v, 0.2) == 0.6*v + 0.4*|v| (exact), fully packed
#define GAT_EDGE(A, EV, VALID)                                              \
    do {                                                                    \
        float d[4];                                                         \
        _Pragma("unroll")                                                   \
        for (int k = 0; k < 4; k++) {                                       \
            u64 t0, t1, s0, s1, dd;                                         \
            F2ADD(t0, A[k].x, EV.x); F2ADD(t0, t0, xr2[k].x);               \
            F2ADD(t1, A[k].y, EV.y); F2ADD(t1, t1, xr2[k].y);               \
            F2MUL(s0, t0, C06);      F2MUL(s1, t1, C06);                    \
            u64 ab0 = t0 & ABSM, ab1 = t1 & ABSM;                           \
            F2FMA(s0, ab0, C04, s0); F2FMA(s1, ab1, C04, s1);               \
            F2MUL(dd, s0, AT_a);     F2FMA(dd, s1, AT_b, dd);               \
            float dl, dh; F2UNPK(dl, dh, dd);                               \
            d[k] = dl + dh;                                                 \
        }                                                                   \
        _Pragma("unroll")                                                   \
        for (int o = 1; o < 8; o <<= 1) {                                   \
            _Pragma("unroll")                                               \
            for (int k = 0; k < 4; k++)                                     \
                d[k] += __shfl_xor_sync(0xffffffffu, d[k], o);              \
        }                                                                   \
        _Pragma("unroll")                                                   \
        for (int k = 0; k < 4; k++) {                                       \
            float wv = (VALID) ? __expf(d[k]) : 0.f;                        \
            u64 wvp; F2PK(wvp, wv, wv);                                     \
            F2FMA(acc[k].x, A[k].x, wvp, acc[k].x);                         \
            F2FMA(acc[k].y, A[k].y, wvp, acc[k].y);                         \
            ssum[k] += wv;                                                  \
        }                                                                   \
    } while (0)

    for (int j = off; j < end; j += 2) {
        int j1 = (j + 1 < end) ? j + 1 : j;
        int2 e1 = g_csr[j1];
        const ulonglong2* xp1 = (const ulonglong2*)(g_xl + e1.x * SNAP * 32);
        ulonglong2 ev1 = *(const ulonglong2*)(g_ee + e1.y * 32 + 4 * q);
        ulonglong2 an[4];
#pragma unroll
        for (int k = 0; k < 4; k++) an[k] = xp1[k * 32 + lane];

        GAT_EDGE(a, ev, true);

        int j2 = (j + 2 < end) ? j + 2 : end - 1;
        int2 e2 = g_csr[j2];
        const ulonglong2* xp2 = (const ulonglong2*)(g_xl + e2.x * SNAP * 32);
        ev = *(const ulonglong2*)(g_ee + e2.y * 32 + 4 * q);
#pragma unroll
        for (int k = 0; k < 4; k++) a[k] = xp2[k * 32 + lane];

        GAT_EDGE(an, ev1, (j + 1 < end));
    }
#undef GAT_EDGE

    const float4 bi4 = *(const float4*)(bias_gat + 4 * q);
#pragma unroll
    for (int k = 0; k < 4; k++) {
        float inv = 1.f / ssum[k];
        int s = 4 * k + g;
        float a0, a1, a2, a3;
        F2UNPK(a0, a1, acc[k].x);
        F2UNPK(a2, a3, acc[k].y);
        float* tp = &s_tr[w][s][4 * q];
        tp[0] = a0 * inv + bi4.x;
        tp[1] = a1 * inv + bi4.y;
        tp[2] = a2 * inv + bi4.z;
        tp[3] = a3 * inv + bi4.w;
    }
    __syncwarp();

    // ---- GRU phase: lane = channel c; 2 sequences; packed (input, hidden) gates
    int c = lane;
    u64 BR, BZ, BN;
    F2PK(BR, sb[0][c], sb[3][c]);
    F2PK(BZ, sb[1][c], sb[4][c]);
    F2PK(BN, sb[2][c], sb[5][c]);

    float h0 = 0.f, h1 = 0.f;
    for (int t = 0; t < TT; t++) {
        u64 gr0 = BR, gz0 = BZ, gn0 = BN;
        u64 gr1 = BR, gz1 = BZ, gn1 = BN;
#pragma unroll
        for (int hh = 0; hh < 32; hh++) {
            float xv0 = s_tr[w][t][hh];
            float xv1 = s_tr[w][8 + t][hh];
            float hv0 = __shfl_sync(0xffffffffu, h0, hh);
            float hv1 = __shfl_sync(0xffffffffu, h1, hh);
            ulonglong2 wrz = *(const ulonglong2*)&sWrz[hh][c];  // (wi_r,wh_r),(wi_z,wh_z)
            u64 wn = *(const u64*)&sWn[hh][c];                  // (wi_n,wh_n)
            u64 xh0, xh1;
            F2PK(xh0, xv0, hv0);
            F2PK(xh1, xv1, hv1);
            F2FMA(gr0, xh0, wrz.x, gr0);
            F2FMA(gz0, xh0, wrz.y, gz0);
            F2FMA(gn0, xh0, wn, gn0);
            F2FMA(gr1, xh1, wrz.x, gr1);
            F2FMA(gz1, xh1, wrz.y, gz1);
            F2FMA(gn1, xh1, wn, gn1);
        }
        {
            float irl, hrl, izl, hzl, inl, hnl;
            F2UNPK(irl, hrl, gr0);
            F2UNPK(izl, hzl, gz0);
            F2UNPK(inl, hnl, gn0);
            float r = 1.f / (1.f + __expf(-(irl + hrl)));
            float z = 1.f / (1.f + __expf(-(izl + hzl)));
            float pre = inl + r * hnl;
            float e2 = __expf(-2.f * pre);
            float nn_ = 2.f / (1.f + e2) - 1.f;
            h0 = (1.f - z) * nn_ + z * h0;
            out[((long)t * NN + n) * 32 + c] = h0;
        }
        {
            float irl, hrl, izl, hzl, inl, hnl;
            F2UNPK(irl, hrl, gr1);
            F2UNPK(izl, hzl, gz1);
            F2UNPK(inl, hnl, gn1);
            float r = 1.f / (1.f + __expf(-(irl + hrl)));
            float z = 1.f / (1.f + __expf(-(izl + hzl)));
            float pre = inl + r * hnl;
            float e2 = __expf(-2.f * pre);
            float nn_ = 2.f / (1.f + e2) - 1.f;
            h1 = (1.f - z) * nn_ + z * h1;
            out[((long)(TT + t) * NN + n) * 32 + c] = h1;
        }
    }

    // epilogue: re-zero per-node counters for the NEXT replay (this warp owns n)
    if (lane < 3) g_loop_sum[n * 3 + lane] = 0.f;
    else if (lane == 3) g_loop_cnt[n] = 0.f;
    else if (lane == 4) g_cursor[n] = 0;
}

// ---------------- launch (forked-stream capture for prep concurrency) ----------------
extern "C" void kernel_launch(void* const* d_in, const int* in_sizes, int n_in,
                              void* d_out, int out_size) {
    const float* x        = (const float*)d_in[0];
    const int*   ei       = (const int*)d_in[1];
    const float* eattr    = (const float*)d_in[2];
    const float* W_l      = (const float*)d_in[3];
    const float* b_l      = (const float*)d_in[4];
    const float* W_r      = (const float*)d_in[5];
    const float* b_r      = (const float*)d_in[6];
    const float* W_e      = (const float*)d_in[7];
    const float* att      = (const float*)d_in[8];
    const float* bias_gat = (const float*)d_in[9];
    const float* W_ih     = (const float*)d_in[10];
    const float* W_hh     = (const float*)d_in[11];
    const float* b_ih     = (const float*)d_in[12];
    const float* b_hh     = (const float*)d_in[13];
    float* out = (float*)d_out;

    static cudaStream_t s1 = nullptr, s2 = nullptr;
    static cudaEvent_t eRoot = nullptr, eDeg = nullptr, eXlr = nullptr, eEe = nullptr;
    if (s1 == nullptr) {
        cudaStreamCreateWithFlags(&s1, cudaStreamNonBlocking);
        cudaStreamCreateWithFlags(&s2, cudaStreamNonBlocking);
        cudaEventCreateWithFlags(&eRoot, cudaEventDisableTiming);
        cudaEventCreateWithFlags(&eDeg, cudaEventDisableTiming);
        cudaEventCreateWithFlags(&eXlr, cudaEventDisableTiming);
        cudaEventCreateWithFlags(&eEe, cudaEventDisableTiming);
    }

    // branch 1: xlr depends only on inputs
    cudaEventRecord(eRoot, 0);
    cudaStreamWaitEvent(s1, eRoot, 0);
    k_xlr<<<296, 256, 0, s1>>>(x, W_l, b_l, W_r, b_r);
    cudaEventRecord(eXlr, s1);

    // main: CSR chain (counters pre-zeroed by previous replay's gatgru)
    k_deg<<<(EE + 255) / 256, 256>>>(ei, eattr);
    cudaEventRecord(eDeg, 0);

    // branch 2: ee depends only on deg
    cudaStreamWaitEvent(s2, eDeg, 0);
    k_ee<<<(ET * 8 + 255) / 256, 256, 0, s2>>>(eattr, W_e);
    cudaEventRecord(eEe, s2);

    k_scan<<<1, 1024>>>();
    k_scatter<<<(EE + NN + 255) / 256, 256>>>(ei);

    // join
    cudaStreamWaitEvent(0, eXlr, 0);
    cudaStreamWaitEvent(0, eEe, 0);
    k_gatgru<<<NN / 8, 256>>>(att, bias_gat, W_ih, W_hh, b_ih, b_hh, out);
}

// round 9
// speedup vs baseline: 1.0458x; 1.0458x over previous
#include <cuda_runtime.h>
#include <math_constants.h>

#define NN    10000
#define EE    160000
#define ET    170000   // EE + NN self loops
#define SNAP  16       // B*T
#define TT    8
#define BB    2
#define CIN   64
#define CC    32

// ---------------- static device scratch (zero-initialized at load) ----------------
__device__ float g_xl[NN * SNAP * CC];       // [n][s][c]
__device__ float g_xr[NN * SNAP * CC];       // [n][s][c]
__device__ float g_ee[ET * CC];              // [edge][c]
__device__ float g_loop_sum[NN * 3];
__device__ float g_loop_cnt[12288];          // padded: k_scan float4 tail reads zeros
__device__ int   g_cursor[NN];
__device__ int   g_csr_off[NN + 1];
__device__ int2  g_csr[ET];                  // (src, eid)

// ---------------- prep kernels ----------------
// loop_sum/loop_cnt/cursor are zero at entry of every replay: statically
// zero-initialized for the first run, re-zeroed by k_gatgru's epilogue after.

__global__ void k_deg(const int* __restrict__ ei, const float* __restrict__ ea) {
    int e = blockIdx.x * blockDim.x + threadIdx.x;
    if (e >= EE) return;
    int dst = ei[EE + e];
    atomicAdd(&g_loop_sum[dst * 3 + 0], ea[e * 3 + 0]);
    atomicAdd(&g_loop_sum[dst * 3 + 1], ea[e * 3 + 1]);
    atomicAdd(&g_loop_sum[dst * 3 + 2], ea[e * 3 + 2]);
    atomicAdd(&g_loop_cnt[dst], 1.f);
}

// single-block scan: 1024 threads, 12 items each via 3x float4 loads
__global__ void k_scan() {
    __shared__ int warp_sums[32];
    int tid = threadIdx.x, lane = tid & 31, wid = tid >> 5;
    int base = tid * 12;
    float4 f0 = *(const float4*)(g_loop_cnt + base);
    float4 f1 = *(const float4*)(g_loop_cnt + base + 4);
    float4 f2 = *(const float4*)(g_loop_cnt + base + 8);
    float c[12] = {f0.x, f0.y, f0.z, f0.w, f1.x, f1.y, f1.z, f1.w,
                   f2.x, f2.y, f2.z, f2.w};
    int v[12];
    int s = 0;
#pragma unroll
    for (int k = 0; k < 12; k++) {
        int idx = base + k;
        int val = (idx < NN) ? ((int)c[k] + 1) : 0;
        v[k] = s;
        s += val;
    }
    int incl = s;
#pragma unroll
    for (int o = 1; o < 32; o <<= 1) {
        int u = __shfl_up_sync(0xffffffffu, incl, o);
        if (lane >= o) incl += u;
    }
    if (lane == 31) warp_sums[wid] = incl;
    __syncthreads();
    if (tid < 32) {
        int w = warp_sums[tid];
#pragma unroll
        for (int o = 1; o < 32; o <<= 1) {
            int u = __shfl_up_sync(0xffffffffu, w, o);
            if (tid >= o) w += u;
        }
        warp_sums[tid] = w;
    }
    __syncthreads();
    int warp_off = (wid == 0) ? 0 : warp_sums[wid - 1];
    int thr_excl = warp_off + incl - s;
#pragma unroll
    for (int k = 0; k < 12; k++) {
        int idx = base + k;
        if (idx < NN) g_csr_off[idx] = thr_excl + v[k];
    }
    if (tid == 0) g_csr_off[NN] = warp_sums[31];
}

__global__ void k_scatter(const int* __restrict__ ei) {
    int e = blockIdx.x * blockDim.x + threadIdx.x;
    if (e < EE) {
        int src = ei[e];
        int dst = ei[EE + e];
        int pos = g_csr_off[dst] + atomicAdd(&g_cursor[dst], 1);
        g_csr[pos] = make_int2(src, e);
    } else if (e < EE + NN) {
        int n = e - EE;
        int pos = g_csr_off[n + 1] - 1;  // self-loop in the last slot
        g_csr[pos] = make_int2(n, EE + n);
    }
}

// ee[r][c] = attr_r @ W_e (self-loop rows: segment mean of incoming attr)
__global__ void k_ee(const float* __restrict__ edge_attr, const float* __restrict__ W_e) {
    int idx = blockIdx.x * blockDim.x + threadIdx.x;
    int r = idx >> 3, c4 = idx & 7;
    if (r >= ET) return;
    float a0, a1, a2;
    if (r < EE) {
        a0 = edge_attr[r * 3 + 0];
        a1 = edge_attr[r * 3 + 1];
        a2 = edge_attr[r * 3 + 2];
    } else {
        int n = r - EE;
        float cnt = fmaxf(g_loop_cnt[n], 1.f);
        float inv = 1.f / cnt;
        a0 = g_loop_sum[n * 3 + 0] * inv;
        a1 = g_loop_sum[n * 3 + 1] * inv;
        a2 = g_loop_sum[n * 3 + 2] * inv;
    }
    const float4* We4 = (const float4*)W_e;
    float4 w0 = We4[c4], w1 = We4[8 + c4], w2 = We4[16 + c4];
    float4 o;
    o.x = a0 * w0.x + a1 * w1.x + a2 * w2.x;
    o.y = a0 * w0.y + a1 * w1.y + a2 * w2.y;
    o.z = a0 * w0.z + a1 * w1.z + a2 * w2.z;
    o.w = a0 * w0.w + a1 * w1.w + a2 * w2.w;
    ((float4*)g_ee)[r * 8 + c4] = o;
}

// Persistent xl/xr transform; packed {Wl,Wr} float2 smem; 2 rows/warp/iter.
__global__ void __launch_bounds__(256) k_xlr(const float* __restrict__ x,
                      const float* __restrict__ W_l, const float* __restrict__ b_l,
                      const float* __restrict__ W_r, const float* __restrict__ b_r) {
    __shared__ float2 sW[CIN * CC];
    int tid = threadIdx.x;
    for (int i = tid; i < CIN * CC; i += 256)
        sW[i] = make_float2(W_l[i], W_r[i]);
    __syncthreads();
    int lane = tid & 31;
    float bl = b_l[lane], br = b_r[lane];
    int gw = blockIdx.x * 8 + (tid >> 5);
    int stride = gridDim.x * 8 * 2;
    for (int r0 = gw * 2; r0 < SNAP * NN; r0 += stride) {
        const float* xp = x + (long)r0 * CIN;
        float a_x0 = xp[lane], a_x1 = xp[lane + 32];
        float b_x0 = xp[CIN + lane], b_x1 = xp[CIN + lane + 32];
        float al_a = 0.f, ar_a = 0.f, al_b = 0.f, ar_b = 0.f;
#pragma unroll
        for (int k = 0; k < CIN; k++) {
            float xa = (k < 32) ? __shfl_sync(0xffffffffu, a_x0, k)
                                : __shfl_sync(0xffffffffu, a_x1, k - 32);
            float xb = (k < 32) ? __shfl_sync(0xffffffffu, b_x0, k)
                                : __shfl_sync(0xffffffffu, b_x1, k - 32);
            float2 w = sW[k * 32 + lane];
            al_a += xa * w.x; ar_a += xa * w.y;
            al_b += xb * w.x; ar_b += xb * w.y;
        }
        int s0 = r0 / NN, n0 = r0 - s0 * NN;
        int r1 = r0 + 1;
        int s1 = r1 / NN, n1 = r1 - s1 * NN;
        g_xl[(n0 * SNAP + s0) * 32 + lane] = al_a + bl;
        g_xr[(n0 * SNAP + s0) * 32 + lane] = ar_a + br;
        g_xl[(n1 * SNAP + s1) * 32 + lane] = al_b + bl;
        g_xr[(n1 * SNAP + s1) * 32 + lane] = ar_b + br;
    }
}

// Fused GATv2 + GRU: warp per node; GAT edge loop with depth-2 prefetch
// (edge j+2's gathers issued before edges j and j+1 are computed).
__global__ void __launch_bounds__(256, 2) k_gatgru(
        const float* __restrict__ att, const float* __restrict__ bias_gat,
        const float* __restrict__ W_ih, const float* __restrict__ W_hh,
        const float* __restrict__ b_ih, const float* __restrict__ b_hh,
        float* __restrict__ out) {
    __shared__ float4 sWA[32][32];     // [h][c] = {wi_r, wh_r, wi_z, wh_z}
    __shared__ float2 sWB[32][32];     // [h][c] = {wi_n, wh_n}
    __shared__ float  sb[6][32];
    __shared__ float  s_tr[8][16][32]; // per-warp transpose [warp][s][c]

    int tid = threadIdx.x;
    for (int i = tid; i < 1024; i += 256) {
        int c = i & 31, hh = i >> 5;
        sWA[hh][c] = make_float4(W_ih[c * 32 + hh],        W_hh[c * 32 + hh],
                                 W_ih[(32 + c) * 32 + hh], W_hh[(32 + c) * 32 + hh]);
        sWB[hh][c] = make_float2(W_ih[(64 + c) * 32 + hh], W_hh[(64 + c) * 32 + hh]);
    }
    if (tid < 96) {
        int g = tid >> 5, c = tid & 31;
        sb[g][c] = b_ih[tid];
        sb[3 + g][c] = b_hh[tid];
    }
    __syncthreads();

    int w = tid >> 5, lane = tid & 31;
    int n = blockIdx.x * 8 + w;            // grid = NN/8 exact
    int q = lane & 7, g = lane >> 3;

    const float4 at4 = *(const float4*)(att + 4 * q);

    float4 xr4[4];
    {
        const float4* p = (const float4*)(g_xr + n * SNAP * 32);
#pragma unroll
        for (int k = 0; k < 4; k++) xr4[k] = p[k * 32 + lane];
    }

    float4 acc[4];
#pragma unroll
    for (int k = 0; k < 4; k++) acc[k] = make_float4(0.f, 0.f, 0.f, 0.f);
    float ssum[4] = {0.f, 0.f, 0.f, 0.f};

    int off = g_csr_off[n], end = g_csr_off[n + 1];  // end > off (self-loop)

    float4 a[4], ev;
    {
        int2 e0 = g_csr[off];
        const float4* xp = (const float4*)(g_xl + e0.x * SNAP * 32);
        ev = *(const float4*)(g_ee + e0.y * 32 + 4 * q);
#pragma unroll
        for (int k = 0; k < 4; k++) a[k] = xp[k * 32 + lane];
    }

#define GAT_EDGE(A, EV, VALID)                                              \
    do {                                                                    \
        float d[4];                                                         \
        _Pragma("unroll")                                                   \
        for (int k = 0; k < 4; k++) {                                       \
            float v0 = A[k].x + EV.x + xr4[k].x;                            \
            float v1 = A[k].y + EV.y + xr4[k].y;                            \
            float v2 = A[k].z + EV.z + xr4[k].z;                            \
            float v3 = A[k].w + EV.w + xr4[k].w;                            \
            v0 = fmaxf(v0, 0.2f * v0);                                      \
            v1 = fmaxf(v1, 0.2f * v1);                                      \
            v2 = fmaxf(v2, 0.2f * v2);                                      \
            v3 = fmaxf(v3, 0.2f * v3);                                      \
            d[k] = v0 * at4.x + v1 * at4.y + v2 * at4.z + v3 * at4.w;       \
        }                                                                   \
        _Pragma("unroll")                                                   \
        for (int o = 1; o < 8; o <<= 1) {                                   \
            _Pragma("unroll")                                               \
            for (int k = 0; k < 4; k++)                                     \
                d[k] += __shfl_xor_sync(0xffffffffu, d[k], o);              \
        }                                                                   \
        _Pragma("unroll")                                                   \
        for (int k = 0; k < 4; k++) {                                       \
            float wv = (VALID) ? __expf(d[k]) : 0.f;                        \
            ssum[k] += wv;                                                  \
            acc[k].x += wv * A[k].x;                                        \
            acc[k].y += wv * A[k].y;                                        \
            acc[k].z += wv * A[k].z;                                        \
            acc[k].w += wv * A[k].w;                                        \
        }                                                                   \
    } while (0)

    for (int j = off; j < end; j += 2) {
        // prefetch edge j+1
        int j1 = (j + 1 < end) ? j + 1 : j;
        int2 e1 = g_csr[j1];
        const float4* xp1 = (const float4*)(g_xl + e1.x * SNAP * 32);
        float4 ev1 = *(const float4*)(g_ee + e1.y * 32 + 4 * q);
        float4 an[4];
#pragma unroll
        for (int k = 0; k < 4; k++) an[k] = xp1[k * 32 + lane];

        // prefetch edge j+2 BEFORE any compute (depth-2 distance)
        int j2 = (j + 2 < end) ? j + 2 : end - 1;
        int2 e2 = g_csr[j2];
        const float4* xp2 = (const float4*)(g_xl + e2.x * SNAP * 32);
        float4 ev2 = *(const float4*)(g_ee + e2.y * 32 + 4 * q);
        float4 a2[4];
#pragma unroll
        for (int k = 0; k < 4; k++) a2[k] = xp2[k * 32 + lane];

        GAT_EDGE(a, ev, true);
        GAT_EDGE(an, ev1, (j + 1 < end));

#pragma unroll
        for (int k = 0; k < 4; k++) a[k] = a2[k];
        ev = ev2;
    }
#undef GAT_EDGE

    const float4 bi4 = *(const float4*)(bias_gat + 4 * q);
#pragma unroll
    for (int k = 0; k < 4; k++) {
        float inv = 1.f / ssum[k];
        int s = 4 * k + g;
        float* tp = &s_tr[w][s][4 * q];
        tp[0] = acc[k].x * inv + bi4.x;
        tp[1] = acc[k].y * inv + bi4.y;
        tp[2] = acc[k].z * inv + bi4.z;
        tp[3] = acc[k].w * inv + bi4.w;
    }
    __syncwarp();

    // ---- GRU phase: lane = channel c; 2 sequences (b=0 -> s=t, b=1 -> s=8+t)
    int c = lane;
    float bi0 = sb[0][c], bi1 = sb[1][c], bi2 = sb[2][c];
    float bh0 = sb[3][c], bh1 = sb[4][c], bh2 = sb[5][c];

    float h0 = 0.f, h1 = 0.f;
    for (int t = 0; t < TT; t++) {
        float ir0 = bi0, iz0 = bi1, in0 = bi2, hr0 = bh0, hz0 = bh1, hn0 = bh2;
        float ir1 = bi0, iz1 = bi1, in1 = bi2, hr1 = bh0, hz1 = bh1, hn1 = bh2;
#pragma unroll
        for (int hh = 0; hh < 32; hh++) {
            float xv0 = s_tr[w][t][hh];
            float xv1 = s_tr[w][8 + t][hh];
            float hv0 = __shfl_sync(0xffffffffu, h0, hh);
            float hv1 = __shfl_sync(0xffffffffu, h1, hh);
            float4 wA = sWA[hh][c];
            float2 wB = sWB[hh][c];
            ir0 += xv0 * wA.x; hr0 += hv0 * wA.y;
            iz0 += xv0 * wA.z; hz0 += hv0 * wA.w;
            in0 += xv0 * wB.x; hn0 += hv0 * wB.y;
            ir1 += xv1 * wA.x; hr1 += hv1 * wA.y;
            iz1 += xv1 * wA.z; hz1 += hv1 * wA.w;
            in1 += xv1 * wB.x; hn1 += hv1 * wB.y;
        }
        {
            float r = 1.f / (1.f + __expf(-(ir0 + hr0)));
            float z = 1.f / (1.f + __expf(-(iz0 + hz0)));
            float pre = in0 + r * hn0;
            float e2 = __expf(-2.f * pre);
            float nn_ = 2.f / (1.f + e2) - 1.f;
            h0 = (1.f - z) * nn_ + z * h0;
            out[((long)t * NN + n) * 32 + c] = h0;
        }
        {
            float r = 1.f / (1.f + __expf(-(ir1 + hr1)));
            float z = 1.f / (1.f + __expf(-(iz1 + hz1)));
            float pre = in1 + r * hn1;
            float e2 = __expf(-2.f * pre);
            float nn_ = 2.f / (1.f + e2) - 1.f;
            h1 = (1.f - z) * nn_ + z * h1;
            out[((long)(TT + t) * NN + n) * 32 + c] = h1;
        }
    }

    // epilogue: re-zero per-node counters for the NEXT replay (this warp owns n)
    if (lane < 3) g_loop_sum[n * 3 + lane] = 0.f;
    else if (lane == 3) g_loop_cnt[n] = 0.f;
    else if (lane == 4) g_cursor[n] = 0;
}

// ---------------- launch (forked-stream capture for prep concurrency) ----------------
extern "C" void kernel_launch(void* const* d_in, const int* in_sizes, int n_in,
                              void* d_out, int out_size) {
    const float* x        = (const float*)d_in[0];
    const int*   ei       = (const int*)d_in[1];
    const float* eattr    = (const float*)d_in[2];
    const float* W_l      = (const float*)d_in[3];
    const float* b_l      = (const float*)d_in[4];
    const float* W_r      = (const float*)d_in[5];
    const float* b_r      = (const float*)d_in[6];
    const float* W_e      = (const float*)d_in[7];
    const float* att      = (const float*)d_in[8];
    const float* bias_gat = (const float*)d_in[9];
    const float* W_ih     = (const float*)d_in[10];
    const float* W_hh     = (const float*)d_in[11];
    const float* b_ih     = (const float*)d_in[12];
    const float* b_hh     = (const float*)d_in[13];
    float* out = (float*)d_out;

    static cudaStream_t s1 = nullptr, s2 = nullptr;
    static cudaEvent_t eRoot = nullptr, eDeg = nullptr, eXlr = nullptr, eEe = nullptr;
    if (s1 == nullptr) {
        cudaStreamCreateWithFlags(&s1, cudaStreamNonBlocking);
        cudaStreamCreateWithFlags(&s2, cudaStreamNonBlocking);
        cudaEventCreateWithFlags(&eRoot, cudaEventDisableTiming);
        cudaEventCreateWithFlags(&eDeg, cudaEventDisableTiming);
        cudaEventCreateWithFlags(&eXlr, cudaEventDisableTiming);
        cudaEventCreateWithFlags(&eEe, cudaEventDisableTiming);
    }

    // branch 1: xlr depends only on inputs
    cudaEventRecord(eRoot, 0);
    cudaStreamWaitEvent(s1, eRoot, 0);
    k_xlr<<<296, 256, 0, s1>>>(x, W_l, b_l, W_r, b_r);
    cudaEventRecord(eXlr, s1);

    // main: CSR chain (counters pre-zeroed by previous replay's gatgru)
    k_deg<<<(EE + 255) / 256, 256>>>(ei, eattr);
    cudaEventRecord(eDeg, 0);

    // branch 2: ee depends only on deg
    cudaStreamWaitEvent(s2, eDeg, 0);
    k_ee<<<(ET * 8 + 255) / 256, 256, 0, s2>>>(eattr, W_e);
    cudaEventRecord(eEe, s2);

    k_scan<<<1, 1024>>>();
    k_scatter<<<(EE + NN + 255) / 256, 256>>>(ei);

    // join
    cudaStreamWaitEvent(0, eXlr, 0);
    cudaStreamWaitEvent(0, eEe, 0);
    k_gatgru<<<NN / 8, 256>>>(att, bias_gat, W_ih, W_hh, b_ih, b_hh, out);
}

// round 10
// speedup vs baseline: 1.1017x; 1.0534x over previous
#include <cuda_runtime.h>
#include <math_constants.h>

#define NN    10000
#define EE    160000
#define SNAP  16       // B*T
#define TT    8
#define BB    2
#define CIN   64
#define CC    32
#define SLOTS 96       // padded bucket capacity per node (max degree ~40)

// ---------------- static device scratch (zero-initialized at load) ----------------
__device__ float g_xl[NN * SNAP * CC];       // [n][s][c]
__device__ float g_xr[NN * SNAP * CC];       // [n][s][c]
__device__ float g_loop_sum[NN * 3];
__device__ int   g_cursor[NN];               // per-node in-degree / bucket cursor
__device__ int4  g_bkt[NN * SLOTS];          // {src, attr0, attr1, attr2}

// ---------------- build: bucket scatter + loop_sum in ONE kernel ----------------
// cursor/loop_sum are zero at entry of every replay: statically zero-initialized
// for the first run, re-zeroed by k_gatgru's epilogue thereafter (stream-ordered).
__global__ void k_build(const int* __restrict__ ei, const float* __restrict__ ea) {
    int e = blockIdx.x * blockDim.x + threadIdx.x;
    if (e >= EE) return;
    int src = ei[e];
    int dst = ei[EE + e];
    float a0 = ea[e * 3 + 0], a1 = ea[e * 3 + 1], a2 = ea[e * 3 + 2];
    atomicAdd(&g_loop_sum[dst * 3 + 0], a0);
    atomicAdd(&g_loop_sum[dst * 3 + 1], a1);
    atomicAdd(&g_loop_sum[dst * 3 + 2], a2);
    int pos = atomicAdd(&g_cursor[dst], 1);
    g_bkt[dst * SLOTS + pos] =
        make_int4(src, __float_as_int(a0), __float_as_int(a1), __float_as_int(a2));
}

// ---------------- xl/xr transform (persistent; packed {Wl,Wr} float2 smem) ----------------
__global__ void __launch_bounds__(256) k_xlr(const float* __restrict__ x,
                      const float* __restrict__ W_l, const float* __restrict__ b_l,
                      const float* __restrict__ W_r, const float* __restrict__ b_r) {
    __shared__ float2 sW[CIN * CC];
    int tid = threadIdx.x;
    for (int i = tid; i < CIN * CC; i += 256)
        sW[i] = make_float2(W_l[i], W_r[i]);
    __syncthreads();
    int lane = tid & 31;
    float bl = b_l[lane], br = b_r[lane];
    int gw = blockIdx.x * 8 + (tid >> 5);
    int stride = gridDim.x * 8 * 2;
    for (int r0 = gw * 2; r0 < SNAP * NN; r0 += stride) {
        const float* xp = x + (long)r0 * CIN;
        float a_x0 = xp[lane], a_x1 = xp[lane + 32];
        float b_x0 = xp[CIN + lane], b_x1 = xp[CIN + lane + 32];
        float al_a = 0.f, ar_a = 0.f, al_b = 0.f, ar_b = 0.f;
#pragma unroll
        for (int k = 0; k < CIN; k++) {
            float xa = (k < 32) ? __shfl_sync(0xffffffffu, a_x0, k)
                                : __shfl_sync(0xffffffffu, a_x1, k - 32);
            float xb = (k < 32) ? __shfl_sync(0xffffffffu, b_x0, k)
                                : __shfl_sync(0xffffffffu, b_x1, k - 32);
            float2 w = sW[k * 32 + lane];
            al_a += xa * w.x; ar_a += xa * w.y;
            al_b += xb * w.x; ar_b += xb * w.y;
        }
        int s0 = r0 / NN, n0 = r0 - s0 * NN;
        int r1 = r0 + 1;
        int s1 = r1 / NN, n1 = r1 - s1 * NN;
        g_xl[(n0 * SNAP + s0) * 32 + lane] = al_a + bl;
        g_xr[(n0 * SNAP + s0) * 32 + lane] = ar_a + br;
        g_xl[(n1 * SNAP + s1) * 32 + lane] = al_b + bl;
        g_xr[(n1 * SNAP + s1) * 32 + lane] = ar_b + br;
    }
}

// Fused GATv2 + GRU: warp per node; ee computed on the fly from bucket attrs.
__global__ void __launch_bounds__(256, 2) k_gatgru(
        const float* __restrict__ W_e,
        const float* __restrict__ att, const float* __restrict__ bias_gat,
        const float* __restrict__ W_ih, const float* __restrict__ W_hh,
        const float* __restrict__ b_ih, const float* __restrict__ b_hh,
        float* __restrict__ out) {
    __shared__ float4 sWA[32][32];     // [h][c] = {wi_r, wh_r, wi_z, wh_z}
    __shared__ float2 sWB[32][32];     // [h][c] = {wi_n, wh_n}
    __shared__ float  sb[6][32];
    __shared__ float  s_tr[8][16][32]; // per-warp transpose [warp][s][c]

    int tid = threadIdx.x;
    for (int i = tid; i < 1024; i += 256) {
        int c = i & 31, hh = i >> 5;
        sWA[hh][c] = make_float4(W_ih[c * 32 + hh],        W_hh[c * 32 + hh],
                                 W_ih[(32 + c) * 32 + hh], W_hh[(32 + c) * 32 + hh]);
        sWB[hh][c] = make_float2(W_ih[(64 + c) * 32 + hh], W_hh[(64 + c) * 32 + hh]);
    }
    if (tid < 96) {
        int g = tid >> 5, c = tid & 31;
        sb[g][c] = b_ih[tid];
        sb[3 + g][c] = b_hh[tid];
    }
    __syncthreads();

    int w = tid >> 5, lane = tid & 31;
    int n = blockIdx.x * 8 + w;            // grid = NN/8 exact
    int q = lane & 7, g = lane >> 3;

    const float4 at4 = *(const float4*)(att + 4 * q);
    // W_e rows for this lane's 4 channels
    const float4 we0 = *(const float4*)(W_e + 4 * q);
    const float4 we1 = *(const float4*)(W_e + 32 + 4 * q);
    const float4 we2 = *(const float4*)(W_e + 64 + 4 * q);

    int deg = g_cursor[n];
    int end = deg + 1;                     // + self loop (last)
    float inv_cnt = 1.f / fmaxf((float)deg, 1.f);
    float lm0 = g_loop_sum[n * 3 + 0] * inv_cnt;
    float lm1 = g_loop_sum[n * 3 + 1] * inv_cnt;
    float lm2 = g_loop_sum[n * 3 + 2] * inv_cnt;

    float4 xr4[4];
    {
        const float4* p = (const float4*)(g_xr + n * SNAP * 32);
#pragma unroll
        for (int k = 0; k < 4; k++) xr4[k] = p[k * 32 + lane];
    }

    float4 acc[4];
#pragma unroll
    for (int k = 0; k < 4; k++) acc[k] = make_float4(0.f, 0.f, 0.f, 0.f);
    float ssum[4] = {0.f, 0.f, 0.f, 0.f};

    const int4* bkt = g_bkt + n * SLOTS;

#define FETCH_EB(J, EB)                                                     \
    do {                                                                    \
        if ((J) < deg) EB = bkt[(J)];                                       \
        else EB = make_int4(n, __float_as_int(lm0), __float_as_int(lm1),    \
                            __float_as_int(lm2));                           \
    } while (0)

    int4 eb0;
    float4 a[4];
    FETCH_EB(0, eb0);
    {
        const float4* xp = (const float4*)(g_xl + eb0.x * SNAP * 32);
#pragma unroll
        for (int k = 0; k < 4; k++) a[k] = xp[k * 32 + lane];
    }

#define GAT_EDGE(A, EB, VALID)                                              \
    do {                                                                    \
        float a0 = __int_as_float(EB.y);                                    \
        float a1 = __int_as_float(EB.z);                                    \
        float a2 = __int_as_float(EB.w);                                    \
        float4 ev;                                                          \
        ev.x = a0 * we0.x + a1 * we1.x + a2 * we2.x;                        \
        ev.y = a0 * we0.y + a1 * we1.y + a2 * we2.y;                        \
        ev.z = a0 * we0.z + a1 * we1.z + a2 * we2.z;                        \
        ev.w = a0 * we0.w + a1 * we1.w + a2 * we2.w;                        \
        float d[4];                                                         \
        _Pragma("unroll")                                                   \
        for (int k = 0; k < 4; k++) {                                       \
            float v0 = A[k].x + ev.x + xr4[k].x;                            \
            float v1 = A[k].y + ev.y + xr4[k].y;                            \
            float v2 = A[k].z + ev.z + xr4[k].z;                            \
            float v3 = A[k].w + ev.w + xr4[k].w;                            \
            v0 = fmaxf(v0, 0.2f * v0);                                      \
            v1 = fmaxf(v1, 0.2f * v1);                                      \
            v2 = fmaxf(v2, 0.2f * v2);                                      \
            v3 = fmaxf(v3, 0.2f * v3);                                      \
            d[k] = v0 * at4.x + v1 * at4.y + v2 * at4.z + v3 * at4.w;       \
        }                                                                   \
        _Pragma("unroll")                                                   \
        for (int o = 1; o < 8; o <<= 1) {                                   \
            _Pragma("unroll")                                               \
            for (int k = 0; k < 4; k++)                                     \
                d[k] += __shfl_xor_sync(0xffffffffu, d[k], o);              \
        }                                                                   \
        _Pragma("unroll")                                                   \
        for (int k = 0; k < 4; k++) {                                       \
            float wv = (VALID) ? __expf(d[k]) : 0.f;                        \
            ssum[k] += wv;                                                  \
            acc[k].x += wv * A[k].x;                                        \
            acc[k].y += wv * A[k].y;                                        \
            acc[k].z += wv * A[k].z;                                        \
            acc[k].w += wv * A[k].w;                                        \
        }                                                                   \
    } while (0)

    for (int j = 0; j < end; j += 2) {
        // prefetch edge j+1
        int j1 = (j + 1 < end) ? j + 1 : j;
        int4 eb1;
        FETCH_EB(j1, eb1);
        const float4* xp1 = (const float4*)(g_xl + eb1.x * SNAP * 32);
        float4 an[4];
#pragma unroll
        for (int k = 0; k < 4; k++) an[k] = xp1[k * 32 + lane];

        // prefetch edge j+2 before compute (depth-2)
        int j2 = (j + 2 < end) ? j + 2 : end - 1;
        int4 eb2;
        FETCH_EB(j2, eb2);
        const float4* xp2 = (const float4*)(g_xl + eb2.x * SNAP * 32);
        float4 a2[4];
#pragma unroll
        for (int k = 0; k < 4; k++) a2[k] = xp2[k * 32 + lane];

        GAT_EDGE(a, eb0, true);
        GAT_EDGE(an, eb1, (j + 1 < end));

#pragma unroll
        for (int k = 0; k < 4; k++) a[k] = a2[k];
        eb0 = eb2;
    }
#undef GAT_EDGE
#undef FETCH_EB

    const float4 bi4 = *(const float4*)(bias_gat + 4 * q);
#pragma unroll
    for (int k = 0; k < 4; k++) {
        float inv = 1.f / ssum[k];
        int s = 4 * k + g;
        float* tp = &s_tr[w][s][4 * q];
        tp[0] = acc[k].x * inv + bi4.x;
        tp[1] = acc[k].y * inv + bi4.y;
        tp[2] = acc[k].z * inv + bi4.z;
        tp[3] = acc[k].w * inv + bi4.w;
    }
    __syncwarp();

    // ---- GRU phase: lane = channel c; 2 sequences (b=0 -> s=t, b=1 -> s=8+t)
    int c = lane;
    float bi0 = sb[0][c], bi1 = sb[1][c], bi2 = sb[2][c];
    float bh0 = sb[3][c], bh1 = sb[4][c], bh2 = sb[5][c];

    float h0 = 0.f, h1 = 0.f;
    for (int t = 0; t < TT; t++) {
        float ir0 = bi0, iz0 = bi1, in0 = bi2, hr0 = bh0, hz0 = bh1, hn0 = bh2;
        float ir1 = bi0, iz1 = bi1, in1 = bi2, hr1 = bh0, hz1 = bh1, hn1 = bh2;
#pragma unroll
        for (int hh = 0; hh < 32; hh++) {
            float xv0 = s_tr[w][t][hh];
            float xv1 = s_tr[w][8 + t][hh];
            float hv0 = __shfl_sync(0xffffffffu, h0, hh);
            float hv1 = __shfl_sync(0xffffffffu, h1, hh);
            float4 wA = sWA[hh][c];
            float2 wB = sWB[hh][c];
            ir0 += xv0 * wA.x; hr0 += hv0 * wA.y;
            iz0 += xv0 * wA.z; hz0 += hv0 * wA.w;
            in0 += xv0 * wB.x; hn0 += hv0 * wB.y;
            ir1 += xv1 * wA.x; hr1 += hv1 * wA.y;
            iz1 += xv1 * wA.z; hz1 += hv1 * wA.w;
            in1 += xv1 * wB.x; hn1 += hv1 * wB.y;
        }
        {
            float r = 1.f / (1.f + __expf(-(ir0 + hr0)));
            float z = 1.f / (1.f + __expf(-(iz0 + hz0)));
            float pre = in0 + r * hn0;
            float e2 = __expf(-2.f * pre);
            float nn_ = 2.f / (1.f + e2) - 1.f;
            h0 = (1.f - z) * nn_ + z * h0;
            out[((long)t * NN + n) * 32 + c] = h0;
        }
        {
            float r = 1.f / (1.f + __expf(-(ir1 + hr1)));
            float z = 1.f / (1.f + __expf(-(iz1 + hz1)));
            float pre = in1 + r * hn1;
            float e2 = __expf(-2.f * pre);
            float nn_ = 2.f / (1.f + e2) - 1.f;
            h1 = (1.f - z) * nn_ + z * h1;
            out[((long)(TT + t) * NN + n) * 32 + c] = h1;
        }
    }

    // epilogue: re-zero per-node counters for the NEXT replay (this warp owns n)
    if (lane < 3) g_loop_sum[n * 3 + lane] = 0.f;
    else if (lane == 3) g_cursor[n] = 0;
}

// ---------------- launch: 3 kernels, xlr forked ----------------
extern "C" void kernel_launch(void* const* d_in, const int* in_sizes, int n_in,
                              void* d_out, int out_size) {
    const float* x        = (const float*)d_in[0];
    const int*   ei       = (const int*)d_in[1];
    const float* eattr    = (const float*)d_in[2];
    const float* W_l      = (const float*)d_in[3];
    const float* b_l      = (const float*)d_in[4];
    const float* W_r      = (const float*)d_in[5];
    const float* b_r      = (const float*)d_in[6];
    const float* W_e      = (const float*)d_in[7];
    const float* att      = (const float*)d_in[8];
    const float* bias_gat = (const float*)d_in[9];
    const float* W_ih     = (const float*)d_in[10];
    const float* W_hh     = (const float*)d_in[11];
    const float* b_ih     = (const float*)d_in[12];
    const float* b_hh     = (const float*)d_in[13];
    float* out = (float*)d_out;

    static cudaStream_t s1 = nullptr;
    static cudaEvent_t eRoot = nullptr, eXlr = nullptr;
    if (s1 == nullptr) {
        cudaStreamCreateWithFlags(&s1, cudaStreamNonBlocking);
        cudaEventCreateWithFlags(&eRoot, cudaEventDisableTiming);
        cudaEventCreateWithFlags(&eXlr, cudaEventDisableTiming);
    }

    // branch: xlr depends only on inputs
    cudaEventRecord(eRoot, 0);
    cudaStreamWaitEvent(s1, eRoot, 0);
    k_xlr<<<296, 256, 0, s1>>>(x, W_l, b_l, W_r, b_r);
    cudaEventRecord(eXlr, s1);

    // main: single bucket-build kernel (counters pre-zeroed by prior replay)
    k_build<<<(EE + 255) / 256, 256>>>(ei, eattr);

    cudaStreamWaitEvent(0, eXlr, 0);
    k_gatgru<<<NN / 8, 256>>>(W_e, att, bias_gat, W_ih, W_hh, b_ih, b_hh, out);
}

// round 11
// speedup vs baseline: 1.1983x; 1.0877x over previous
#include <cuda_runtime.h>
#include <math_constants.h>

#define NN    10000
#define EE    160000
#define SNAP  16       // B*T
#define TT    8
#define BB    2
#define CIN   64
#define CC    32
#define SLOTS 96       // padded bucket capacity per node (max degree ~40)

// ---------------- static device scratch (zero-initialized at load) ----------------
__device__ float g_xl[NN * SNAP * CC];       // [n][s][c]
__device__ float g_xr[NN * SNAP * CC];       // [n][s][c]
__device__ float g_loop_sum[NN * 3];
__device__ int   g_cursor[NN];               // per-node in-degree / bucket cursor
__device__ int4  g_bkt[NN * SLOTS];          // {src, attr0, attr1, attr2}

// ---------------- build: bucket scatter + loop_sum in ONE kernel ----------------
// cursor/loop_sum are zero at entry of every replay: statically zero-initialized
// for the first run, re-zeroed by k_gatgru's epilogue thereafter (stream-ordered).
__global__ void k_build(const int* __restrict__ ei, const float* __restrict__ ea) {
    int e = blockIdx.x * blockDim.x + threadIdx.x;
    if (e >= EE) return;
    int src = ei[e];
    int dst = ei[EE + e];
    float a0 = ea[e * 3 + 0], a1 = ea[e * 3 + 1], a2 = ea[e * 3 + 2];
    atomicAdd(&g_loop_sum[dst * 3 + 0], a0);
    atomicAdd(&g_loop_sum[dst * 3 + 1], a1);
    atomicAdd(&g_loop_sum[dst * 3 + 2], a2);
    int pos = atomicAdd(&g_cursor[dst], 1);
    g_bkt[dst * SLOTS + pos] =
        make_int4(src, __float_as_int(a0), __float_as_int(a1), __float_as_int(a2));
}

// ---------------- xl/xr transform: 4 rows/warp/iter, high occupancy ----------------
__global__ void __launch_bounds__(256) k_xlr(const float* __restrict__ x,
                      const float* __restrict__ W_l, const float* __restrict__ b_l,
                      const float* __restrict__ W_r, const float* __restrict__ b_r) {
    __shared__ float2 sW[CIN * CC];
    int tid = threadIdx.x;
    for (int i = tid; i < CIN * CC; i += 256)
        sW[i] = make_float2(W_l[i], W_r[i]);
    __syncthreads();
    int lane = tid & 31;
    float bl = b_l[lane], br = b_r[lane];
    int gw = blockIdx.x * 8 + (tid >> 5);
    int stride = gridDim.x * 8 * 4;
    for (int r0 = gw * 4; r0 < SNAP * NN; r0 += stride) {
        const float* xp = x + (long)r0 * CIN;
        float xa0 = xp[lane],             xa1 = xp[lane + 32];
        float xb0 = xp[CIN + lane],       xb1 = xp[CIN + lane + 32];
        float xc0 = xp[2 * CIN + lane],   xc1 = xp[2 * CIN + lane + 32];
        float xd0 = xp[3 * CIN + lane],   xd1 = xp[3 * CIN + lane + 32];
        float alA = 0.f, arA = 0.f, alB = 0.f, arB = 0.f;
        float alC = 0.f, arC = 0.f, alD = 0.f, arD = 0.f;
#pragma unroll
        for (int k = 0; k < CIN; k++) {
            float va = (k < 32) ? __shfl_sync(0xffffffffu, xa0, k)
                                : __shfl_sync(0xffffffffu, xa1, k - 32);
            float vb = (k < 32) ? __shfl_sync(0xffffffffu, xb0, k)
                                : __shfl_sync(0xffffffffu, xb1, k - 32);
            float vc = (k < 32) ? __shfl_sync(0xffffffffu, xc0, k)
                                : __shfl_sync(0xffffffffu, xc1, k - 32);
            float vd = (k < 32) ? __shfl_sync(0xffffffffu, xd0, k)
                                : __shfl_sync(0xffffffffu, xd1, k - 32);
            float2 w = sW[k * 32 + lane];
            alA += va * w.x; arA += va * w.y;
            alB += vb * w.x; arB += vb * w.y;
            alC += vc * w.x; arC += vc * w.y;
            alD += vd * w.x; arD += vd * w.y;
        }
        // 4 consecutive rows share s (NN % 4 == 0, r0 % 4 == 0 -> no s crossing)
        int s = r0 / NN, n = r0 - s * NN;
        g_xl[((n + 0) * SNAP + s) * 32 + lane] = alA + bl;
        g_xr[((n + 0) * SNAP + s) * 32 + lane] = arA + br;
        g_xl[((n + 1) * SNAP + s) * 32 + lane] = alB + bl;
        g_xr[((n + 1) * SNAP + s) * 32 + lane] = arB + br;
        g_xl[((n + 2) * SNAP + s) * 32 + lane] = alC + bl;
        g_xr[((n + 2) * SNAP + s) * 32 + lane] = arC + br;
        g_xl[((n + 3) * SNAP + s) * 32 + lane] = alD + bl;
        g_xr[((n + 3) * SNAP + s) * 32 + lane] = arD + br;
    }
}

// Fused GATv2 + GRU: warp per node; ee computed on the fly from bucket attrs.
__global__ void __launch_bounds__(256, 2) k_gatgru(
        const float* __restrict__ W_e,
        const float* __restrict__ att, const float* __restrict__ bias_gat,
        const float* __restrict__ W_ih, const float* __restrict__ W_hh,
        const float* __restrict__ b_ih, const float* __restrict__ b_hh,
        float* __restrict__ out) {
    __shared__ float4 sWA[32][32];     // [h][c] = {wi_r, wh_r, wi_z, wh_z}
    __shared__ float2 sWB[32][32];     // [h][c] = {wi_n, wh_n}
    __shared__ float  sb[6][32];
    __shared__ float  s_tr[8][16][32]; // per-warp transpose [warp][s][c]

    int tid = threadIdx.x;
    for (int i = tid; i < 1024; i += 256) {
        int c = i & 31, hh = i >> 5;
        sWA[hh][c] = make_float4(W_ih[c * 32 + hh],        W_hh[c * 32 + hh],
                                 W_ih[(32 + c) * 32 + hh], W_hh[(32 + c) * 32 + hh]);
        sWB[hh][c] = make_float2(W_ih[(64 + c) * 32 + hh], W_hh[(64 + c) * 32 + hh]);
    }
    if (tid < 96) {
        int g = tid >> 5, c = tid & 31;
        sb[g][c] = b_ih[tid];
        sb[3 + g][c] = b_hh[tid];
    }
    __syncthreads();

    int w = tid >> 5, lane = tid & 31;
    int n = blockIdx.x * 8 + w;            // grid = NN/8 exact
    int q = lane & 7, g = lane >> 3;

    const float4 at4 = *(const float4*)(att + 4 * q);
    const float4 we0 = *(const float4*)(W_e + 4 * q);
    const float4 we1 = *(const float4*)(W_e + 32 + 4 * q);
    const float4 we2 = *(const float4*)(W_e + 64 + 4 * q);

    int deg = g_cursor[n];
    int end = deg + 1;                     // + self loop (last)
    float inv_cnt = 1.f / fmaxf((float)deg, 1.f);
    float lm0 = g_loop_sum[n * 3 + 0] * inv_cnt;
    float lm1 = g_loop_sum[n * 3 + 1] * inv_cnt;
    float lm2 = g_loop_sum[n * 3 + 2] * inv_cnt;

    float4 xr4[4];
    {
        const float4* p = (const float4*)(g_xr + n * SNAP * 32);
#pragma unroll
        for (int k = 0; k < 4; k++) xr4[k] = p[k * 32 + lane];
    }

    float4 acc[4];
#pragma unroll
    for (int k = 0; k < 4; k++) acc[k] = make_float4(0.f, 0.f, 0.f, 0.f);
    float ssum[4] = {0.f, 0.f, 0.f, 0.f};

    const int4* bkt = g_bkt + n * SLOTS;

#define FETCH_EB(J, EB)                                                     \
    do {                                                                    \
        if ((J) < deg) EB = bkt[(J)];                                       \
        else EB = make_int4(n, __float_as_int(lm0), __float_as_int(lm1),    \
                            __float_as_int(lm2));                           \
    } while (0)

    int4 eb0;
    float4 a[4];
    FETCH_EB(0, eb0);
    {
        const float4* xp = (const float4*)(g_xl + eb0.x * SNAP * 32);
#pragma unroll
        for (int k = 0; k < 4; k++) a[k] = xp[k * 32 + lane];
    }

#define GAT_EDGE(A, EB, VALID)                                              \
    do {                                                                    \
        float a0 = __int_as_float(EB.y);                                    \
        float a1 = __int_as_float(EB.z);                                    \
        float a2 = __int_as_float(EB.w);                                    \
        float4 ev;                                                          \
        ev.x = a0 * we0.x + a1 * we1.x + a2 * we2.x;                        \
        ev.y = a0 * we0.y + a1 * we1.y + a2 * we2.y;                        \
        ev.z = a0 * we0.z + a1 * we1.z + a2 * we2.z;                        \
        ev.w = a0 * we0.w + a1 * we1.w + a2 * we2.w;                        \
        float d[4];                                                         \
        _Pragma("unroll")                                                   \
        for (int k = 0; k < 4; k++) {                                       \
            float v0 = A[k].x + ev.x + xr4[k].x;                            \
            float v1 = A[k].y + ev.y + xr4[k].y;                            \
            float v2 = A[k].z + ev.z + xr4[k].z;                            \
            float v3 = A[k].w + ev.w + xr4[k].w;                            \
            v0 = fmaxf(v0, 0.2f * v0);                                      \
            v1 = fmaxf(v1, 0.2f * v1);                                      \
            v2 = fmaxf(v2, 0.2f * v2);                                      \
            v3 = fmaxf(v3, 0.2f * v3);                                      \
            d[k] = v0 * at4.x + v1 * at4.y + v2 * at4.z + v3 * at4.w;       \
        }                                                                   \
        _Pragma("unroll")                                                   \
        for (int o = 1; o < 8; o <<= 1) {                                   \
            _Pragma("unroll")                                               \
            for (int k = 0; k < 4; k++)                                     \
                d[k] += __shfl_xor_sync(0xffffffffu, d[k], o);              \
        }                                                                   \
        _Pragma("unroll")                                                   \
        for (int k = 0; k < 4; k++) {                                       \
            float wv = (VALID) ? __expf(d[k]) : 0.f;                        \
            ssum[k] += wv;                                                  \
            acc[k].x += wv * A[k].x;                                        \
            acc[k].y += wv * A[k].y;                                        \
            acc[k].z += wv * A[k].z;                                        \
            acc[k].w += wv * A[k].w;                                        \
        }                                                                   \
    } while (0)

    for (int j = 0; j < end; j += 2) {
        int j1 = (j + 1 < end) ? j + 1 : j;
        int4 eb1;
        FETCH_EB(j1, eb1);
        const float4* xp1 = (const float4*)(g_xl + eb1.x * SNAP * 32);
        float4 an[4];
#pragma unroll
        for (int k = 0; k < 4; k++) an[k] = xp1[k * 32 + lane];

        int j2 = (j + 2 < end) ? j + 2 : end - 1;
        int4 eb2;
        FETCH_EB(j2, eb2);
        const float4* xp2 = (const float4*)(g_xl + eb2.x * SNAP * 32);
        float4 a2[4];
#pragma unroll
        for (int k = 0; k < 4; k++) a2[k] = xp2[k * 32 + lane];

        GAT_EDGE(a, eb0, true);
        GAT_EDGE(an, eb1, (j + 1 < end));

#pragma unroll
        for (int k = 0; k < 4; k++) a[k] = a2[k];
        eb0 = eb2;
    }
#undef GAT_EDGE
#undef FETCH_EB

    const float4 bi4 = *(const float4*)(bias_gat + 4 * q);
#pragma unroll
    for (int k = 0; k < 4; k++) {
        float inv = 1.f / ssum[k];
        int s = 4 * k + g;
        float* tp = &s_tr[w][s][4 * q];
        tp[0] = acc[k].x * inv + bi4.x;
        tp[1] = acc[k].y * inv + bi4.y;
        tp[2] = acc[k].z * inv + bi4.z;
        tp[3] = acc[k].w * inv + bi4.w;
    }
    __syncwarp();

    // ---- GRU phase: lane = channel c; 2 sequences (b=0 -> s=t, b=1 -> s=8+t)
    int c = lane;
    float bi0 = sb[0][c], bi1 = sb[1][c], bi2 = sb[2][c];
    float bh0 = sb[3][c], bh1 = sb[4][c], bh2 = sb[5][c];

    float h0 = 0.f, h1 = 0.f;
    for (int t = 0; t < TT; t++) {
        float ir0 = bi0, iz0 = bi1, in0 = bi2, hr0 = bh0, hz0 = bh1, hn0 = bh2;
        float ir1 = bi0, iz1 = bi1, in1 = bi2, hr1 = bh0, hz1 = bh1, hn1 = bh2;
#pragma unroll
        for (int hh = 0; hh < 32; hh++) {
            float xv0 = s_tr[w][t][hh];
            float xv1 = s_tr[w][8 + t][hh];
            float hv0 = __shfl_sync(0xffffffffu, h0, hh);
            float hv1 = __shfl_sync(0xffffffffu, h1, hh);
            float4 wA = sWA[hh][c];
            float2 wB = sWB[hh][c];
            ir0 += xv0 * wA.x; hr0 += hv0 * wA.y;
            iz0 += xv0 * wA.z; hz0 += hv0 * wA.w;
            in0 += xv0 * wB.x; hn0 += hv0 * wB.y;
            ir1 += xv1 * wA.x; hr1 += hv1 * wA.y;
            iz1 += xv1 * wA.z; hz1 += hv1 * wA.w;
            in1 += xv1 * wB.x; hn1 += hv1 * wB.y;
        }
        {
            float r = 1.f / (1.f + __expf(-(ir0 + hr0)));
            float z = 1.f / (1.f + __expf(-(iz0 + hz0)));
            float pre = in0 + r * hn0;
            float e2 = __expf(-2.f * pre);
            float nn_ = 2.f / (1.f + e2) - 1.f;
            h0 = (1.f - z) * nn_ + z * h0;
            out[((long)t * NN + n) * 32 + c] = h0;
        }
        {
            float r = 1.f / (1.f + __expf(-(ir1 + hr1)));
            float z = 1.f / (1.f + __expf(-(iz1 + hz1)));
            float pre = in1 + r * hn1;
            float e2 = __expf(-2.f * pre);
            float nn_ = 2.f / (1.f + e2) - 1.f;
            h1 = (1.f - z) * nn_ + z * h1;
            out[((long)(TT + t) * NN + n) * 32 + c] = h1;
        }
    }

    // epilogue: re-zero per-node counters for the NEXT replay (this warp owns n)
    if (lane < 3) g_loop_sum[n * 3 + lane] = 0.f;
    else if (lane == 3) g_cursor[n] = 0;
}

// ---------------- launch: 3 kernels, xlr forked ----------------
extern "C" void kernel_launch(void* const* d_in, const int* in_sizes, int n_in,
                              void* d_out, int out_size) {
    const float* x        = (const float*)d_in[0];
    const int*   ei       = (const int*)d_in[1];
    const float* eattr    = (const float*)d_in[2];
    const float* W_l      = (const float*)d_in[3];
    const float* b_l      = (const float*)d_in[4];
    const float* W_r      = (const float*)d_in[5];
    const float* b_r      = (const float*)d_in[6];
    const float* W_e      = (const float*)d_in[7];
    const float* att      = (const float*)d_in[8];
    const float* bias_gat = (const float*)d_in[9];
    const float* W_ih     = (const float*)d_in[10];
    const float* W_hh     = (const float*)d_in[11];
    const float* b_ih     = (const float*)d_in[12];
    const float* b_hh     = (const float*)d_in[13];
    float* out = (float*)d_out;

    static cudaStream_t s1 = nullptr;
    static cudaEvent_t eRoot = nullptr, eXlr = nullptr;
    if (s1 == nullptr) {
        cudaStreamCreateWithFlags(&s1, cudaStreamNonBlocking);
        cudaEventCreateWithFlags(&eRoot, cudaEventDisableTiming);
        cudaEventCreateWithFlags(&eXlr, cudaEventDisableTiming);
    }

    // branch: xlr depends only on inputs
    cudaEventRecord(eRoot, 0);
    cudaStreamWaitEvent(s1, eRoot, 0);
    k_xlr<<<1184, 256, 0, s1>>>(x, W_l, b_l, W_r, b_r);
    cudaEventRecord(eXlr, s1);

    // main: single bucket-build kernel (counters pre-zeroed by prior replay)
    k_build<<<(EE + 255) / 256, 256>>>(ei, eattr);

    cudaStreamWaitEvent(0, eXlr, 0);
    k_gatgru<<<NN / 8, 256>>>(W_e, att, bias_gat, W_ih, W_hh, b_ih, b_hh, out);
}